// round 8
// baseline (speedup 1.0000x reference)
#include <cuda_runtime.h>
#include <cuda_fp16.h>
#include <cstdint>

#define D_FEAT      48
#define XH_STRIDE   64            // halfs per row: 48 data + 16 zero pad = 128B
#define N_NODES_DS  100000
#define N_NODES_MAX 100001

// CSR row pointers built each launch from the sorted COO rows array.
__device__ int d_row_ptr[N_NODES_MAX + 1];

// fp16 copy of x, rows padded to 128B. Pad region (halfs 48..63 of each row)
// is NEVER written: __device__ globals are zero-initialized at module load,
// so it is always zero -- deterministic across replays.
__device__ __align__(128) __half d_xh[(size_t)N_NODES_DS * XH_STRIDE];

// ---------------------------------------------------------------------------
// Fused setup kernel. Block ranges:
//   [0, conv_blocks)              : convert x fp32 -> fp16 (6 chunks/row)
//   [conv_blocks, conv+ptr_blocks): row_ptr[r] = lower_bound(rows, E, r)
// The two tasks are independent and now run CONCURRENTLY in one launch.
// ---------------------------------------------------------------------------
__global__ void __launch_bounds__(256) setup_kernel(
    const float* __restrict__ x,
    const int*   __restrict__ rows,
    int n_edges, int n_nodes, int conv_blocks)
{
    if ((int)blockIdx.x < conv_blocks) {
        // ---- convert: thread per 16B output chunk; 6 chunks per row ----
        const int tid = blockIdx.x * 256 + threadIdx.x;
        const int row   = tid / 6;
        const int chunk = tid - row * 6;
        if (row >= n_nodes) return;

        const float4 f0 = *reinterpret_cast<const float4*>(
            x + (size_t)row * D_FEAT + chunk * 8);
        const float4 f1 = *reinterpret_cast<const float4*>(
            x + (size_t)row * D_FEAT + chunk * 8 + 4);
        __half2 h0 = __floats2half2_rn(f0.x, f0.y);
        __half2 h1 = __floats2half2_rn(f0.z, f0.w);
        __half2 h2 = __floats2half2_rn(f1.x, f1.y);
        __half2 h3 = __floats2half2_rn(f1.z, f1.w);
        uint4 outv;
        outv.x = *reinterpret_cast<const unsigned*>(&h0);
        outv.y = *reinterpret_cast<const unsigned*>(&h1);
        outv.z = *reinterpret_cast<const unsigned*>(&h2);
        outv.w = *reinterpret_cast<const unsigned*>(&h3);
        *reinterpret_cast<uint4*>(d_xh + (size_t)row * XH_STRIDE + chunk * 8) = outv;
    } else {
        // ---- row_ptr via binary search over sorted rows ----
        const int r = (blockIdx.x - conv_blocks) * 256 + threadIdx.x;
        if (r > n_nodes) return;
        int lo = 0, hi = n_edges;
        while (lo < hi) {
            int mid = (lo + hi) >> 1;
            if (__ldg(rows + mid) < r) lo = mid + 1;
            else                       hi = mid;
        }
        d_row_ptr[r] = lo;
    }
}

// ---------------------------------------------------------------------------
// SpMM: quarter-warp (8 lanes) per row, 4 rows/warp, fp16 x gathers.
//   Lanes sub=0..5 own 8 features each -> one LDG.128 per edge hitting
//   exactly ONE 128B line (1 L1 wavefront/edge).
//   Metadata vectorized: per 4-edge batch each group loads int4 cols +
//   float4 vals (uniform in group -> broadcast) and issues 4 INDEPENDENT
//   gathers -> 16 outstanding gathers per warp for latency hiding.
//   fp32 accumulation; plain stores; no atomics; no zero-init pass.
// ---------------------------------------------------------------------------
__global__ void __launch_bounds__(256, 4) spmm_csr_qw4_kernel(
    const int*   __restrict__ cols,
    const float* __restrict__ vals,
    float*       __restrict__ out,
    int n_nodes, int n_edges)
{
    const int warp_id = (blockIdx.x * blockDim.x + threadIdx.x) >> 5;
    const int lane    = threadIdx.x & 31;
    const int sub     = lane & 7;
    const bool active = sub < 6;

    const int row = warp_id * 4 + (lane >> 3);
    if (row >= n_nodes) return;

    const int s = d_row_ptr[row];
    const int e = d_row_ptr[row + 1];

    float a0 = 0.f, a1 = 0.f, a2 = 0.f, a3 = 0.f;
    float a4 = 0.f, a5 = 0.f, a6 = 0.f, a7 = 0.f;
    const size_t hoff = (size_t)sub * 8;

    #pragma unroll 2
    for (int i = (s & ~3); i < e; i += 4) {
        int4   c4;
        float4 v4;
        if (i + 4 <= n_edges) {
            c4 = __ldg(reinterpret_cast<const int4*>(cols + i));
            v4 = __ldg(reinterpret_cast<const float4*>(vals + i));
        } else {
            c4.x = cols[i];
            c4.y = (i + 1 < n_edges) ? cols[i + 1] : 0;
            c4.z = (i + 2 < n_edges) ? cols[i + 2] : 0;
            c4.w = (i + 3 < n_edges) ? cols[i + 3] : 0;
            v4.x = vals[i];
            v4.y = (i + 1 < n_edges) ? vals[i + 1] : 0.f;
            v4.z = (i + 2 < n_edges) ? vals[i + 2] : 0.f;
            v4.w = (i + 3 < n_edges) ? vals[i + 3] : 0.f;
        }

        const int cc[4] = {c4.x, c4.y, c4.z, c4.w};
        const float vv[4] = {v4.x, v4.y, v4.z, v4.w};

        #pragma unroll
        for (int k = 0; k < 4; ++k) {
            if (active && (i + k) >= s && (i + k) < e) {
                const uint4 h4 = *reinterpret_cast<const uint4*>(
                    d_xh + (size_t)cc[k] * XH_STRIDE + hoff);  // 1-line LDG.128
                const float v = vv[k];
                const float2 f0 = __half22float2(*reinterpret_cast<const __half2*>(&h4.x));
                const float2 f1 = __half22float2(*reinterpret_cast<const __half2*>(&h4.y));
                const float2 f2 = __half22float2(*reinterpret_cast<const __half2*>(&h4.z));
                const float2 f3 = __half22float2(*reinterpret_cast<const __half2*>(&h4.w));
                a0 += v * f0.x; a1 += v * f0.y;
                a2 += v * f1.x; a3 += v * f1.y;
                a4 += v * f2.x; a5 += v * f2.y;
                a6 += v * f3.x; a7 += v * f3.y;
            }
        }
    }

    if (active) {
        float* o = out + (size_t)row * D_FEAT + sub * 8;
        *reinterpret_cast<float4*>(o)     = make_float4(a0, a1, a2, a3);
        *reinterpret_cast<float4*>(o + 4) = make_float4(a4, a5, a6, a7);
    }
}

// ---------------------------------------------------------------------------
// kernel_launch: inputs per metadata order: t, x, rows, cols, vals.
// ---------------------------------------------------------------------------
extern "C" void kernel_launch(void* const* d_in, const int* in_sizes, int n_in,
                              void* d_out, int out_size)
{
    const float* x    = (const float*)d_in[1];
    const int*   rows = (const int*)  d_in[2];
    const int*   cols = (const int*)  d_in[3];
    const float* vals = (const float*)d_in[4];
    float*       out  = (float*)d_out;

    const int n_edges = in_sizes[4];
    const int n_nodes = out_size / D_FEAT;

    // Fused setup: convert x to fp16 AND build row_ptr, concurrently.
    {
        const int conv_threads = n_nodes * 6;
        const int conv_blocks  = (conv_threads + 255) / 256;
        const int ptr_blocks   = (n_nodes + 1 + 255) / 256;
        setup_kernel<<<conv_blocks + ptr_blocks, 256>>>(
            x, rows, n_edges, n_nodes, conv_blocks);
    }

    // SpMM: 4 rows per warp, vectorized metadata, fp16 gathers.
    {
        const int threads = 256;
        const int warps   = (n_nodes + 3) / 4;
        const int blocks  = (warps * 32 + threads - 1) / threads;
        spmm_csr_qw4_kernel<<<blocks, threads>>>(cols, vals, out,
                                                 n_nodes, n_edges);
    }
}

// round 9
// speedup vs baseline: 1.1151x; 1.1151x over previous
#include <cuda_runtime.h>
#include <cuda_fp16.h>
#include <cstdint>

#define D_FEAT      48
#define XH_STRIDE   64            // halfs per row: 48 data + 16 zero pad = 128B
#define N_NODES_DS  100000
#define N_NODES_MAX 100001

// CSR row pointers built each launch from the sorted COO rows array.
__device__ int d_row_ptr[N_NODES_MAX + 1];

// fp16 copy of x, rows padded to 128B. Pad region (halfs 48..63 of each row)
// is NEVER written: __device__ globals are zero-initialized at module load,
// so it stays zero -- deterministic across replays.
__device__ __align__(128) __half d_xh[(size_t)N_NODES_DS * XH_STRIDE];

// ---------------------------------------------------------------------------
// Fused setup kernel (proven in R7): convert x fp32->fp16 and build row_ptr
// CONCURRENTLY in one launch, split by block range.
// ---------------------------------------------------------------------------
__global__ void __launch_bounds__(256) setup_kernel(
    const float* __restrict__ x,
    const int*   __restrict__ rows,
    int n_edges, int n_nodes, int conv_blocks)
{
    if ((int)blockIdx.x < conv_blocks) {
        // ---- convert: thread per 16B output chunk; 6 chunks per row ----
        const int tid   = blockIdx.x * 256 + threadIdx.x;
        const int row   = tid / 6;
        const int chunk = tid - row * 6;
        if (row >= n_nodes) return;

        const float4 f0 = *reinterpret_cast<const float4*>(
            x + (size_t)row * D_FEAT + chunk * 8);
        const float4 f1 = *reinterpret_cast<const float4*>(
            x + (size_t)row * D_FEAT + chunk * 8 + 4);
        __half2 h0 = __floats2half2_rn(f0.x, f0.y);
        __half2 h1 = __floats2half2_rn(f0.z, f0.w);
        __half2 h2 = __floats2half2_rn(f1.x, f1.y);
        __half2 h3 = __floats2half2_rn(f1.z, f1.w);
        uint4 outv;
        outv.x = *reinterpret_cast<const unsigned*>(&h0);
        outv.y = *reinterpret_cast<const unsigned*>(&h1);
        outv.z = *reinterpret_cast<const unsigned*>(&h2);
        outv.w = *reinterpret_cast<const unsigned*>(&h3);
        *reinterpret_cast<uint4*>(d_xh + (size_t)row * XH_STRIDE + chunk * 8) = outv;
    } else {
        // ---- row_ptr via binary search over sorted rows ----
        const int r = (blockIdx.x - conv_blocks) * 256 + threadIdx.x;
        if (r > n_nodes) return;
        int lo = 0, hi = n_edges;
        while (lo < hi) {
            int mid = (lo + hi) >> 1;
            if (__ldg(rows + mid) < r) lo = mid + 1;
            else                       hi = mid;
        }
        d_row_ptr[r] = lo;
    }
}

// ---------------------------------------------------------------------------
// SpMM (exact R6 winner): quarter-warp (8 lanes) per row, 4 rows/warp.
//   Lanes sub=0..5 own 8 features each -> one LDG.128 per edge hitting
//   exactly ONE 128B line (1 L1 wavefront/edge). Scalar uniform col/val
//   loads (L1 broadcast within group); #pragma unroll 4 exposes 4
//   independent gathers per group (16/warp). fp32 accumulation; plain
//   stores; no atomics; no zero-init pass.
// ---------------------------------------------------------------------------
__global__ void __launch_bounds__(256) spmm_csr_qw_h_kernel(
    const int*   __restrict__ cols,
    const float* __restrict__ vals,
    float*       __restrict__ out,
    int n_nodes)
{
    const int warp_id = (blockIdx.x * blockDim.x + threadIdx.x) >> 5;
    const int lane    = threadIdx.x & 31;
    const int g       = lane >> 3;          // group 0..3 -> row within warp
    const int sub     = lane & 7;           // lane within group
    const bool active = sub < 6;            // 6 lanes x 8 halfs = 48 features

    const int row = warp_id * 4 + g;
    if (row >= n_nodes) return;

    const int s = d_row_ptr[row];
    const int e = d_row_ptr[row + 1];

    float a0 = 0.f, a1 = 0.f, a2 = 0.f, a3 = 0.f;
    float a4 = 0.f, a5 = 0.f, a6 = 0.f, a7 = 0.f;

    const size_t hoff = (size_t)sub * 8;    // 8 halfs = 16B per lane

    #pragma unroll 4
    for (int i = s; i < e; ++i) {
        const int   c = __ldg(cols + i);    // uniform within 8-lane group
        const float v = __ldg(vals + i);
        if (active) {
            const uint4 h4 = *reinterpret_cast<const uint4*>(
                d_xh + (size_t)c * XH_STRIDE + hoff);     // LDG.E.128, 1 line
            const float2 f0 = __half22float2(*reinterpret_cast<const __half2*>(&h4.x));
            const float2 f1 = __half22float2(*reinterpret_cast<const __half2*>(&h4.y));
            const float2 f2 = __half22float2(*reinterpret_cast<const __half2*>(&h4.z));
            const float2 f3 = __half22float2(*reinterpret_cast<const __half2*>(&h4.w));
            a0 += v * f0.x; a1 += v * f0.y;
            a2 += v * f1.x; a3 += v * f1.y;
            a4 += v * f2.x; a5 += v * f2.y;
            a6 += v * f3.x; a7 += v * f3.y;
        }
    }

    if (active) {
        float* o = out + (size_t)row * D_FEAT + sub * 8;
        *reinterpret_cast<float4*>(o)     = make_float4(a0, a1, a2, a3);
        *reinterpret_cast<float4*>(o + 4) = make_float4(a4, a5, a6, a7);
    }
}

// ---------------------------------------------------------------------------
// kernel_launch: inputs per metadata order: t, x, rows, cols, vals.
// ---------------------------------------------------------------------------
extern "C" void kernel_launch(void* const* d_in, const int* in_sizes, int n_in,
                              void* d_out, int out_size)
{
    const float* x    = (const float*)d_in[1];
    const int*   rows = (const int*)  d_in[2];
    const int*   cols = (const int*)  d_in[3];
    const float* vals = (const float*)d_in[4];
    float*       out  = (float*)d_out;

    const int n_edges = in_sizes[4];
    const int n_nodes = out_size / D_FEAT;

    // Fused setup: convert x to fp16 AND build row_ptr, concurrently.
    {
        const int conv_threads = n_nodes * 6;
        const int conv_blocks  = (conv_threads + 255) / 256;
        const int ptr_blocks   = (n_nodes + 1 + 255) / 256;
        setup_kernel<<<conv_blocks + ptr_blocks, 256>>>(
            x, rows, n_edges, n_nodes, conv_blocks);
    }

    // SpMM: quarter-warp-per-row on fp16 x (R6 winner, unchanged).
    {
        const int threads = 256;                           // 8 warps/block
        const int warps   = (n_nodes + 3) / 4;
        const int blocks  = (warps * 32 + threads - 1) / threads;
        spmm_csr_qw_h_kernel<<<blocks, threads>>>(cols, vals, out, n_nodes);
    }
}

// round 12
// speedup vs baseline: 1.1232x; 1.0072x over previous
#include <cuda_runtime.h>
#include <cuda_fp16.h>
#include <cstdint>

#define D_FEAT      48
#define XH_STRIDE   64            // halfs per row: 48 data + 16 zero pad = 128B
#define N_NODES_DS  100000
#define N_NODES_MAX 100001

// CSR row pointers built each launch from the sorted COO rows array.
__device__ int d_row_ptr[N_NODES_MAX + 1];

// fp16 copy of x, rows padded to 128B. Pad region (halfs 48..63 of each row)
// is NEVER written: __device__ globals are zero-initialized at module load,
// so it stays zero -- deterministic across replays.
__device__ __align__(128) __half d_xh[(size_t)N_NODES_DS * XH_STRIDE];

// ---------------------------------------------------------------------------
// Fused setup kernel: convert x fp32->fp16 and build row_ptr CONCURRENTLY
// in one launch, split by block range.
// ---------------------------------------------------------------------------
__global__ void __launch_bounds__(256) setup_kernel(
    const float* __restrict__ x,
    const int*   __restrict__ rows,
    int n_edges, int n_nodes, int conv_blocks)
{
    if ((int)blockIdx.x < conv_blocks) {
        // ---- convert: thread per 16B output chunk; 6 chunks per row ----
        const int tid   = blockIdx.x * 256 + threadIdx.x;
        const int row   = tid / 6;
        const int chunk = tid - row * 6;
        if (row >= n_nodes) return;

        const float4 f0 = *reinterpret_cast<const float4*>(
            x + (size_t)row * D_FEAT + chunk * 8);
        const float4 f1 = *reinterpret_cast<const float4*>(
            x + (size_t)row * D_FEAT + chunk * 8 + 4);
        __half2 h0 = __floats2half2_rn(f0.x, f0.y);
        __half2 h1 = __floats2half2_rn(f0.z, f0.w);
        __half2 h2 = __floats2half2_rn(f1.x, f1.y);
        __half2 h3 = __floats2half2_rn(f1.z, f1.w);
        uint4 outv;
        outv.x = *reinterpret_cast<const unsigned*>(&h0);
        outv.y = *reinterpret_cast<const unsigned*>(&h1);
        outv.z = *reinterpret_cast<const unsigned*>(&h2);
        outv.w = *reinterpret_cast<const unsigned*>(&h3);
        *reinterpret_cast<uint4*>(d_xh + (size_t)row * XH_STRIDE + chunk * 8) = outv;
    } else {
        // ---- row_ptr via binary search over sorted rows ----
        const int r = (blockIdx.x - conv_blocks) * 256 + threadIdx.x;
        if (r > n_nodes) return;
        int lo = 0, hi = n_edges;
        while (lo < hi) {
            int mid = (lo + hi) >> 1;
            if (__ldg(rows + mid) < r) lo = mid + 1;
            else                       hi = mid;
        }
        d_row_ptr[r] = lo;
    }
}

// ---------------------------------------------------------------------------
// SpMM: quarter-warp (8 lanes) per row, 4 rows/warp, fp16 1-line gathers.
//   Identical to the R6/R9 winner EXCEPT unroll depth 4 -> 8: ptxas hoists
//   8 col loads + 8 independent gather LDG.128s per group per pipeline
//   stage, deepening per-warp MLP to hide L2 gather latency.
// ---------------------------------------------------------------------------
__global__ void __launch_bounds__(256) spmm_csr_qw_h_kernel(
    const int*   __restrict__ cols,
    const float* __restrict__ vals,
    float*       __restrict__ out,
    int n_nodes)
{
    const int warp_id = (blockIdx.x * blockDim.x + threadIdx.x) >> 5;
    const int lane    = threadIdx.x & 31;
    const int g       = lane >> 3;          // group 0..3 -> row within warp
    const int sub     = lane & 7;           // lane within group
    const bool active = sub < 6;            // 6 lanes x 8 halfs = 48 features

    const int row = warp_id * 4 + g;
    if (row >= n_nodes) return;

    const int s = d_row_ptr[row];
    const int e = d_row_ptr[row + 1];

    float a0 = 0.f, a1 = 0.f, a2 = 0.f, a3 = 0.f;
    float a4 = 0.f, a5 = 0.f, a6 = 0.f, a7 = 0.f;

    const size_t hoff = (size_t)sub * 8;    // 8 halfs = 16B per lane

    #pragma unroll 8
    for (int i = s; i < e; ++i) {
        const int   c = __ldg(cols + i);    // uniform within 8-lane group
        const float v = __ldg(vals + i);
        if (active) {
            const uint4 h4 = *reinterpret_cast<const uint4*>(
                d_xh + (size_t)c * XH_STRIDE + hoff);     // LDG.E.128, 1 line
            const float2 f0 = __half22float2(*reinterpret_cast<const __half2*>(&h4.x));
            const float2 f1 = __half22float2(*reinterpret_cast<const __half2*>(&h4.y));
            const float2 f2 = __half22float2(*reinterpret_cast<const __half2*>(&h4.z));
            const float2 f3 = __half22float2(*reinterpret_cast<const __half2*>(&h4.w));
            a0 += v * f0.x; a1 += v * f0.y;
            a2 += v * f1.x; a3 += v * f1.y;
            a4 += v * f2.x; a5 += v * f2.y;
            a6 += v * f3.x; a7 += v * f3.y;
        }
    }

    if (active) {
        float* o = out + (size_t)row * D_FEAT + sub * 8;
        *reinterpret_cast<float4*>(o)     = make_float4(a0, a1, a2, a3);
        *reinterpret_cast<float4*>(o + 4) = make_float4(a4, a5, a6, a7);
    }
}

// ---------------------------------------------------------------------------
// kernel_launch: inputs per metadata order: t, x, rows, cols, vals.
// ---------------------------------------------------------------------------
extern "C" void kernel_launch(void* const* d_in, const int* in_sizes, int n_in,
                              void* d_out, int out_size)
{
    const float* x    = (const float*)d_in[1];
    const int*   rows = (const int*)  d_in[2];
    const int*   cols = (const int*)  d_in[3];
    const float* vals = (const float*)d_in[4];
    float*       out  = (float*)d_out;

    const int n_edges = in_sizes[4];
    const int n_nodes = out_size / D_FEAT;

    // Fused setup: convert x to fp16 AND build row_ptr, concurrently.
    {
        const int conv_threads = n_nodes * 6;
        const int conv_blocks  = (conv_threads + 255) / 256;
        const int ptr_blocks   = (n_nodes + 1 + 255) / 256;
        setup_kernel<<<conv_blocks + ptr_blocks, 256>>>(
            x, rows, n_edges, n_nodes, conv_blocks);
    }

    // SpMM: quarter-warp-per-row on fp16 x, unroll 8.
    {
        const int threads = 256;                           // 8 warps/block
        const int warps   = (n_nodes + 3) / 4;
        const int blocks  = (warps * 32 + threads - 1) / threads;
        spmm_csr_qw_h_kernel<<<blocks, threads>>>(cols, vals, out, n_nodes);
    }
}